// round 1
// baseline (speedup 1.0000x reference)
#include <cuda_runtime.h>

// Problem constants
#define NSMP   8192
#define NA     512
#define DOUT   256
#define LD_IN  (NSMP + 520)   // 8712 input row stride (floats)
#define A_OFF  512            // A0 = input[:, 512:8704]
#define LD_OUT (DOUT + NSMP)  // 8448 output row stride

// Scratch (no cudaMalloc allowed)
__device__ float g_partial[32 * NSMP];   // column-sum partials
__device__ float g_dinv[NSMP];           // rsqrt(degree)
__device__ float g_Sp[NSMP * DOUT];      // S' = diag(dinv) * (X @ W)  (8 MB)

// ---------------------------------------------------------------------------
// Kernel 1: partial column sums of A0. grid (32 colblocks, 32 rowchunks), 256 thr
// ---------------------------------------------------------------------------
__global__ void colsum_partial(const float* __restrict__ inp) {
    int j  = blockIdx.x * 256 + threadIdx.x;      // column of A0
    int r0 = blockIdx.y * 256;                    // first row of chunk
    const float* p = inp + (size_t)r0 * LD_IN + A_OFF + j;
    float s = 0.f;
#pragma unroll 8
    for (int i = 0; i < 256; i++) s += p[(size_t)i * LD_IN];
    g_partial[blockIdx.y * NSMP + j] = s;
}

// ---------------------------------------------------------------------------
// Kernel 2: reduce partials, d = 1 + colsum, dinv = rsqrt(d). grid 32 x 256 thr
// ---------------------------------------------------------------------------
__global__ void colsum_finish() {
    int j = blockIdx.x * 256 + threadIdx.x;
    float s = 1.0f;  // +I contributes 1 to every column sum
#pragma unroll
    for (int r = 0; r < 32; r++) s += g_partial[r * NSMP + j];
    g_dinv[j] = rsqrtf(s);
}

// ---------------------------------------------------------------------------
// Kernel 3: S' = diag(dinv) * (X @ W).  M=8192, N=256, K=512.
// 64x64 block tile, BK=16, 256 threads, 4x4 per thread. grid (128, 4)
// ---------------------------------------------------------------------------
__global__ void support_kernel(const float* __restrict__ inp,
                               const float* __restrict__ W) {
    __shared__ float Xs[16][64];
    __shared__ float Ws[16][64];
    int tx   = threadIdx.x;
    int row0 = blockIdx.x * 64;
    int col0 = blockIdx.y * 64;
    int tr = tx / 16, tc = tx % 16;

    float acc[4][4] = {};

    for (int k0 = 0; k0 < NA; k0 += 16) {
#pragma unroll
        for (int t = tx; t < 64 * 16; t += 256) {
            int m = t / 16, kk = t % 16;
            Xs[kk][m] = inp[(size_t)(row0 + m) * LD_IN + (k0 + kk)];
        }
#pragma unroll
        for (int t = tx; t < 16 * 64; t += 256) {
            int kk = t / 64, n = t % 64;
            Ws[kk][n] = W[(size_t)(k0 + kk) * DOUT + col0 + n];
        }
        __syncthreads();
#pragma unroll
        for (int kk = 0; kk < 16; kk++) {
            float a[4], b[4];
#pragma unroll
            for (int i = 0; i < 4; i++) a[i] = Xs[kk][tr * 4 + i];
#pragma unroll
            for (int i = 0; i < 4; i++) b[i] = Ws[kk][tc * 4 + i];
#pragma unroll
            for (int i = 0; i < 4; i++)
#pragma unroll
                for (int jj = 0; jj < 4; jj++) acc[i][jj] += a[i] * b[jj];
        }
        __syncthreads();
    }
#pragma unroll
    for (int i = 0; i < 4; i++) {
        int r = row0 + tr * 4 + i;
        float dv = g_dinv[r];
#pragma unroll
        for (int jj = 0; jj < 4; jj++)
            g_Sp[(size_t)r * DOUT + col0 + tc * 4 + jj] = dv * acc[i][jj];
    }
}

// ---------------------------------------------------------------------------
// Kernel 4: out[:, :256] = diag(dinv) * (A0 @ S' + S')  fused with the copy
//           out[:, 256:] = A0 + I  (written from the blocks with blockIdx.y==0
//           as the A tiles stream through for the GEMM).
// 128x128 block tile, BK=16, 256 threads, 8x8 per thread. grid (64, 2)
// ---------------------------------------------------------------------------
__global__ void __launch_bounds__(256, 1)
main_gemm(const float* __restrict__ inp, float* __restrict__ out) {
    __shared__ float As[16][128];   // transposed: As[k][m]
    __shared__ float Bs[16][128];   // Bs[k][n]
    int tx   = threadIdx.x;
    int row0 = blockIdx.x * 128;
    int col0 = blockIdx.y * 128;
    const bool do_copy = (blockIdx.y == 0);
    int tr = tx / 16, tc = tx % 16;

    float acc[8][8] = {};

    for (int k0 = 0; k0 < NSMP; k0 += 16) {
        // ---- load A tile (rows row0..+127, cols k0..+15) as float4 ----
#pragma unroll
        for (int t = tx; t < 128 * 4; t += 256) {
            int m = t / 4, q = t % 4;
            int gi = row0 + m;
            int gj = k0 + q * 4;
            float4 v = *(const float4*)&inp[(size_t)gi * LD_IN + A_OFF + gj];
            As[q * 4 + 0][m] = v.x;
            As[q * 4 + 1][m] = v.y;
            As[q * 4 + 2][m] = v.z;
            As[q * 4 + 3][m] = v.w;
            if (do_copy) {
                float4 w = v;
                int dlt = gi - gj;
                if (dlt >= 0 && dlt < 4) ((float*)&w)[dlt] += 1.0f;  // +I
                *(float4*)&out[(size_t)gi * LD_OUT + DOUT + gj] = w;
            }
        }
        // ---- load B tile (S' rows k0..+15, cols col0..+127) ----
#pragma unroll
        for (int t = tx; t < 16 * 32; t += 256) {
            int kk = t / 32, q = t % 32;
            float4 v = *(const float4*)&g_Sp[(size_t)(k0 + kk) * DOUT + col0 + q * 4];
            *(float4*)&Bs[kk][q * 4] = v;
        }
        __syncthreads();
#pragma unroll
        for (int kk = 0; kk < 16; kk++) {
            float a[8], b[8];
#pragma unroll
            for (int i = 0; i < 8; i++) a[i] = As[kk][tr * 8 + i];
#pragma unroll
            for (int j = 0; j < 8; j++) b[j] = Bs[kk][tc * 8 + j];
#pragma unroll
            for (int i = 0; i < 8; i++)
#pragma unroll
                for (int j = 0; j < 8; j++) acc[i][j] += a[i] * b[j];
        }
        __syncthreads();
    }

    // ---- epilogue: out = dinv[i] * (acc + S'[i])  (the +I term) ----
#pragma unroll
    for (int i = 0; i < 8; i++) {
        int gi = row0 + tr * 8 + i;
        float dv = g_dinv[gi];
#pragma unroll
        for (int j = 0; j < 8; j++) {
            int gn = col0 + tc * 8 + j;
            out[(size_t)gi * LD_OUT + gn] =
                dv * (acc[i][j] + g_Sp[(size_t)gi * DOUT + gn]);
        }
    }
}

// ---------------------------------------------------------------------------
extern "C" void kernel_launch(void* const* d_in, const int* in_sizes, int n_in,
                              void* d_out, int out_size) {
    const float* inp = (const float*)d_in[0];   // (8192, 8712)
    const float* W   = (const float*)d_in[1];   // (512, 256)
    float* out       = (float*)d_out;           // (8192, 8448)

    colsum_partial<<<dim3(NSMP / 256, 32), 256>>>(inp);
    colsum_finish<<<NSMP / 256, 256>>>();
    support_kernel<<<dim3(NSMP / 64, DOUT / 64), 256>>>(inp, W);
    main_gemm<<<dim3(NSMP / 128, DOUT / 128), 256>>>(inp, out);
}

// round 11
// speedup vs baseline: 3.0238x; 3.0238x over previous
#include <cuda_runtime.h>
#include <cuda_bf16.h>
#include <cstdint>

// Problem constants
#define NSMP   8192
#define NA     512
#define DOUT   256
#define LD_IN  8712           // input row stride (floats)
#define A_OFF  512            // A0 = input[:, 512:8704]
#define LD_OUT 8448           // output row stride

#define BM 128
#define BN 128
#define BK 32
#define STRIDE 18             // padded SMEM row stride in b32 words (16 data + 2 pad)

// Scratch (no cudaMalloc allowed)
__device__ float         g_partial[32 * NSMP];
__device__ float         g_dinv[NSMP];
__device__ float         g_Sp[NSMP * DOUT];         // S' fp32 [row][256]
__device__ __nv_bfloat16 g_SpT[DOUT * NSMP];        // S'^T bf16 [n][8192]

// ---------------------------------------------------------------------------
__device__ __forceinline__ void mma16816(float* c, const uint32_t* a, const uint32_t* b) {
    asm volatile(
        "mma.sync.aligned.m16n8k16.row.col.f32.bf16.bf16.f32 "
        "{%0,%1,%2,%3}, {%4,%5,%6,%7}, {%8,%9}, {%0,%1,%2,%3};"
        : "+f"(c[0]), "+f"(c[1]), "+f"(c[2]), "+f"(c[3])
        : "r"(a[0]), "r"(a[1]), "r"(a[2]), "r"(a[3]), "r"(b[0]), "r"(b[1]));
}

// ---------------------------------------------------------------------------
// Kernel 1: partial column sums of A0
// ---------------------------------------------------------------------------
__global__ void colsum_partial(const float* __restrict__ inp) {
    int j  = blockIdx.x * 256 + threadIdx.x;
    int r0 = blockIdx.y * 256;
    const float* p = inp + (size_t)r0 * LD_IN + A_OFF + j;
    float s = 0.f;
#pragma unroll 8
    for (int i = 0; i < 256; i++) s += p[(size_t)i * LD_IN];
    g_partial[blockIdx.y * NSMP + j] = s;
}

// ---------------------------------------------------------------------------
// Kernel 2: d = 1 + colsum, dinv = rsqrt(d)
// ---------------------------------------------------------------------------
__global__ void colsum_finish() {
    int j = blockIdx.x * 256 + threadIdx.x;
    float s = 1.0f;
#pragma unroll
    for (int r = 0; r < 32; r++) s += g_partial[r * NSMP + j];
    g_dinv[j] = rsqrtf(s);
}

// ---------------------------------------------------------------------------
// Kernel 3: S' = diag(dinv) * (X @ W); also emit bf16 S'^T (B operand)
// ---------------------------------------------------------------------------
__global__ void support_kernel(const float* __restrict__ inp,
                               const float* __restrict__ W) {
    __shared__ float Xs[16][64];
    __shared__ float Ws[16][64];
    int tx   = threadIdx.x;
    int row0 = blockIdx.x * 64;
    int col0 = blockIdx.y * 64;
    int tr = tx / 16, tc = tx % 16;

    float acc[4][4] = {};

    for (int k0 = 0; k0 < NA; k0 += 16) {
#pragma unroll
        for (int t = tx; t < 64 * 16; t += 256) {
            int m = t / 16, kk = t % 16;
            Xs[kk][m] = inp[(size_t)(row0 + m) * LD_IN + (k0 + kk)];
        }
#pragma unroll
        for (int t = tx; t < 16 * 64; t += 256) {
            int kk = t / 64, n = t % 64;
            Ws[kk][n] = W[(size_t)(k0 + kk) * DOUT + col0 + n];
        }
        __syncthreads();
#pragma unroll
        for (int kk = 0; kk < 16; kk++) {
            float a[4], b[4];
#pragma unroll
            for (int i = 0; i < 4; i++) a[i] = Xs[kk][tr * 4 + i];
#pragma unroll
            for (int i = 0; i < 4; i++) b[i] = Ws[kk][tc * 4 + i];
#pragma unroll
            for (int i = 0; i < 4; i++)
#pragma unroll
                for (int jj = 0; jj < 4; jj++) acc[i][jj] += a[i] * b[jj];
        }
        __syncthreads();
    }
#pragma unroll
    for (int i = 0; i < 4; i++) {
        int r = row0 + tr * 4 + i;
        float dv = g_dinv[r];
#pragma unroll
        for (int jj = 0; jj < 4; jj++) {
            int n = col0 + tc * 4 + jj;
            float sv = dv * acc[i][jj];
            g_Sp[(size_t)r * DOUT + n] = sv;
            g_SpT[(size_t)n * NSMP + r] = __float2bfloat16(sv);
        }
    }
}

// ---------------------------------------------------------------------------
// Kernel 4: bf16 mma.sync GEMM: D[128,128] += A0[128,8192] @ S'^T, fused with
//           the fp32 A+I copy (y==0). Epilogue: out = dinv_i * (D + S'_i).
// 256 threads (8 warps as 2x4), BK=32 double-buffered, grid (64, 2).
// ---------------------------------------------------------------------------
__global__ void __launch_bounds__(256, 1)
main_gemm_mma(const float* __restrict__ inp, float* __restrict__ out) {
    __shared__ uint32_t sA[2][BM * STRIDE];   // [m][k-word], bf16x2 words
    __shared__ uint32_t sB[2][BN * STRIDE];   // [n][k-word]

    int tid  = threadIdx.x;
    int wid  = tid >> 5, lane = tid & 31;
    int g    = lane >> 2, tg = lane & 3;
    int wm   = wid >> 2, wn = wid & 3;        // warp grid 2(M) x 4(N)
    int row0 = blockIdx.x * BM;
    int col0 = blockIdx.y * BN;
    const bool do_copy = (blockIdx.y == 0);

    float acc[4][4][4] = {};                  // [mt][nt][frag]
    float4 ra[4];
    uint4  rb[2];

    // ---- tile loaders (gmem -> regs), with fused A+I copy ----
#define LOADG(IT)                                                              \
    {                                                                          \
        int k0 = (IT) * BK;                                                    \
        _Pragma("unroll")                                                      \
        for (int i = 0; i < 4; i++) {                                          \
            int f = tid + i * 256, m = f >> 3, q = f & 7;                      \
            ra[i] = *(const float4*)(inp + (size_t)(row0 + m) * LD_IN + A_OFF  \
                                     + k0 + q * 4);                            \
        }                                                                      \
        _Pragma("unroll")                                                      \
        for (int i = 0; i < 2; i++) {                                          \
            int f = tid + i * 256, n = f >> 2, q = f & 3;                      \
            rb[i] = *(const uint4*)(g_SpT + (size_t)(col0 + n) * NSMP + k0     \
                                    + q * 8);                                  \
        }                                                                      \
        if (do_copy) {                                                         \
            _Pragma("unroll")                                                  \
            for (int i = 0; i < 4; i++) {                                      \
                int f = tid + i * 256, m = f >> 3, q = f & 7;                  \
                int gi = row0 + m, gj = k0 + q * 4;                            \
                float4 w = ra[i];                                              \
                int dlt = gi - gj;                                             \
                if (dlt >= 0 && dlt < 4) ((float*)&w)[dlt] += 1.0f;            \
                *(float4*)(out + (size_t)gi * LD_OUT + DOUT + gj) = w;         \
            }                                                                  \
        }                                                                      \
    }

#define STOS(S)                                                                \
    {                                                                          \
        _Pragma("unroll")                                                      \
        for (int i = 0; i < 4; i++) {                                          \
            int f = tid + i * 256, m = f >> 3, q = f & 7;                      \
            __nv_bfloat162 p0 = __floats2bfloat162_rn(ra[i].x, ra[i].y);       \
            __nv_bfloat162 p1 = __floats2bfloat162_rn(ra[i].z, ra[i].w);       \
            sA[S][m * STRIDE + q * 2]     = *(uint32_t*)&p0;                   \
            sA[S][m * STRIDE + q * 2 + 1] = *(uint32_t*)&p1;                   \
        }                                                                      \
        _Pragma("unroll")                                                      \
        for (int i = 0; i < 2; i++) {                                          \
            int f = tid + i * 256, n = f >> 2, q = f & 3;                      \
            sB[S][n * STRIDE + q * 4]     = rb[i].x;                           \
            sB[S][n * STRIDE + q * 4 + 1] = rb[i].y;                           \
            sB[S][n * STRIDE + q * 4 + 2] = rb[i].z;                           \
            sB[S][n * STRIDE + q * 4 + 3] = rb[i].w;                           \
        }                                                                      \
    }

    LOADG(0);
    STOS(0);
    __syncthreads();

#pragma unroll 1
    for (int it = 0; it < 256; ++it) {
        int cur = it & 1;
        if (it < 255) LOADG(it + 1);

        // ---- compute on stage cur: two k16 steps ----
#pragma unroll
        for (int ks = 0; ks < 2; ks++) {
            uint32_t af[4][4], bf[4][2];
#pragma unroll
            for (int mt = 0; mt < 4; mt++) {
                int m = wm * 64 + mt * 16 + g;
                af[mt][0] = sA[cur][m * STRIDE + ks * 8 + tg];
                af[mt][1] = sA[cur][(m + 8) * STRIDE + ks * 8 + tg];
                af[mt][2] = sA[cur][m * STRIDE + ks * 8 + tg + 4];
                af[mt][3] = sA[cur][(m + 8) * STRIDE + ks * 8 + tg + 4];
            }
#pragma unroll
            for (int nt = 0; nt < 4; nt++) {
                int n = wn * 32 + nt * 8 + g;
                bf[nt][0] = sB[cur][n * STRIDE + ks * 8 + tg];
                bf[nt][1] = sB[cur][n * STRIDE + ks * 8 + tg + 4];
            }
#pragma unroll
            for (int mt = 0; mt < 4; mt++)
#pragma unroll
                for (int nt = 0; nt < 4; nt++)
                    mma16816(acc[mt][nt], af[mt], bf[nt]);
        }

        if (it < 255) STOS(cur ^ 1);
        __syncthreads();
    }

    // ---- epilogue: out = dinv_i * (acc + S'_i) ----
#pragma unroll
    for (int mt = 0; mt < 4; mt++) {
        int r0 = row0 + wm * 64 + mt * 16 + g;
        int r1 = r0 + 8;
        float dv0 = g_dinv[r0], dv1 = g_dinv[r1];
#pragma unroll
        for (int nt = 0; nt < 4; nt++) {
            int c = col0 + wn * 32 + nt * 8 + tg * 2;
            const float* sp0 = g_Sp + (size_t)r0 * DOUT + c;
            const float* sp1 = g_Sp + (size_t)r1 * DOUT + c;
            float* o0 = out + (size_t)r0 * LD_OUT + c;
            float* o1 = out + (size_t)r1 * LD_OUT + c;
            o0[0] = dv0 * (acc[mt][nt][0] + sp0[0]);
            o0[1] = dv0 * (acc[mt][nt][1] + sp0[1]);
            o1[0] = dv1 * (acc[mt][nt][2] + sp1[0]);
            o1[1] = dv1 * (acc[mt][nt][3] + sp1[1]);
        }
    }
#undef LOADG
#undef STOS
}

// ---------------------------------------------------------------------------
extern "C" void kernel_launch(void* const* d_in, const int* in_sizes, int n_in,
                              void* d_out, int out_size) {
    const float* inp = (const float*)d_in[0];   // (8192, 8712)
    const float* W   = (const float*)d_in[1];   // (512, 256)
    float* out       = (float*)d_out;           // (8192, 8448)

    colsum_partial<<<dim3(NSMP / 256, 32), 256>>>(inp);
    colsum_finish<<<NSMP / 256, 256>>>();
    support_kernel<<<dim3(NSMP / 64, DOUT / 64), 256>>>(inp, W);
    main_gemm_mma<<<dim3(NSMP / BM, DOUT / BN), 256>>>(inp, out);
}

// round 15
// speedup vs baseline: 3.2948x; 1.0896x over previous
#include <cuda_runtime.h>
#include <cuda_bf16.h>
#include <cstdint>

// Problem constants
#define NSMP   8192
#define NA     512
#define DOUT   256
#define LD_IN  8712
#define A_OFF  512
#define LD_OUT 8448

#define BM 128
#define BN 128
#define BK 32
#define STRIDE 20             // padded SMEM row stride in b32 words (16 data + 4 pad)
#define ASZ (BM * STRIDE * 4) // bytes per A stage
#define BSZ (BN * STRIDE * 4)

// Scratch (no cudaMalloc allowed)
__device__ float         g_partial[32 * NSMP];
__device__ float         g_dinv[NSMP];
__device__ float         g_Sp[NSMP * DOUT];
__device__ __nv_bfloat16 g_SpT[DOUT * NSMP];

// ---------------------------------------------------------------------------
__device__ __forceinline__ void mma16816(float* c, const uint32_t* a, const uint32_t* b) {
    asm volatile(
        "mma.sync.aligned.m16n8k16.row.col.f32.bf16.bf16.f32 "
        "{%0,%1,%2,%3}, {%4,%5,%6,%7}, {%8,%9}, {%0,%1,%2,%3};"
        : "+f"(c[0]), "+f"(c[1]), "+f"(c[2]), "+f"(c[3])
        : "r"(a[0]), "r"(a[1]), "r"(a[2]), "r"(a[3]), "r"(b[0]), "r"(b[1]));
}
#define LDSM_X4(d, addr)                                                       \
    asm volatile("ldmatrix.sync.aligned.m8n8.x4.shared.b16 {%0,%1,%2,%3}, [%4];" \
                 : "=r"((d)[0]), "=r"((d)[1]), "=r"((d)[2]), "=r"((d)[3])      \
                 : "r"(addr))
#define LDSM_X2(d, addr)                                                       \
    asm volatile("ldmatrix.sync.aligned.m8n8.x2.shared.b16 {%0,%1}, [%2];"     \
                 : "=r"((d)[0]), "=r"((d)[1]) : "r"(addr))

// ---------------------------------------------------------------------------
__global__ void colsum_partial(const float* __restrict__ inp) {
    int j  = blockIdx.x * 256 + threadIdx.x;
    int r0 = blockIdx.y * 256;
    const float* p = inp + (size_t)r0 * LD_IN + A_OFF + j;
    float s = 0.f;
#pragma unroll 8
    for (int i = 0; i < 256; i++) s += p[(size_t)i * LD_IN];
    g_partial[blockIdx.y * NSMP + j] = s;
}

__global__ void colsum_finish() {
    int j = blockIdx.x * 256 + threadIdx.x;
    float s = 1.0f;
#pragma unroll
    for (int r = 0; r < 32; r++) s += g_partial[r * NSMP + j];
    g_dinv[j] = rsqrtf(s);
}

// ---------------------------------------------------------------------------
__global__ void support_kernel(const float* __restrict__ inp,
                               const float* __restrict__ W) {
    __shared__ float Xs[16][64];
    __shared__ float Ws[16][64];
    int tx   = threadIdx.x;
    int row0 = blockIdx.x * 64;
    int col0 = blockIdx.y * 64;
    int tr = tx / 16, tc = tx % 16;

    float acc[4][4] = {};

    for (int k0 = 0; k0 < NA; k0 += 16) {
#pragma unroll
        for (int t = tx; t < 64 * 16; t += 256) {
            int m = t / 16, kk = t % 16;
            Xs[kk][m] = inp[(size_t)(row0 + m) * LD_IN + (k0 + kk)];
        }
#pragma unroll
        for (int t = tx; t < 16 * 64; t += 256) {
            int kk = t / 64, n = t % 64;
            Ws[kk][n] = W[(size_t)(k0 + kk) * DOUT + col0 + n];
        }
        __syncthreads();
#pragma unroll
        for (int kk = 0; kk < 16; kk++) {
            float a[4], b[4];
#pragma unroll
            for (int i = 0; i < 4; i++) a[i] = Xs[kk][tr * 4 + i];
#pragma unroll
            for (int i = 0; i < 4; i++) b[i] = Ws[kk][tc * 4 + i];
#pragma unroll
            for (int i = 0; i < 4; i++)
#pragma unroll
                for (int jj = 0; jj < 4; jj++) acc[i][jj] += a[i] * b[jj];
        }
        __syncthreads();
    }
#pragma unroll
    for (int i = 0; i < 4; i++) {
        int r = row0 + tr * 4 + i;
        float dv = g_dinv[r];
#pragma unroll
        for (int jj = 0; jj < 4; jj++) {
            int n = col0 + tc * 4 + jj;
            float sv = dv * acc[i][jj];
            g_Sp[(size_t)r * DOUT + n] = sv;
            g_SpT[(size_t)n * NSMP + r] = __float2bfloat16(sv);
        }
    }
}

// ---------------------------------------------------------------------------
// Kernel 4: bf16 mma.sync GEMM with depth-2 register prefetch + ldmatrix.
// ---------------------------------------------------------------------------
__global__ void __launch_bounds__(256, 1)
main_gemm_mma(const float* __restrict__ inp, float* __restrict__ out) {
    __shared__ uint32_t sA[2][BM * STRIDE];
    __shared__ uint32_t sB[2][BN * STRIDE];

    int tid  = threadIdx.x;
    int wid  = tid >> 5, lane = tid & 31;
    int g    = lane >> 2, tg = lane & 3;
    int wm   = wid >> 2, wn = wid & 3;
    int row0 = blockIdx.x * BM;
    int col0 = blockIdx.y * BN;
    const bool do_copy = (blockIdx.y == 0);

    float acc[4][4][4] = {};
    float4 ra[2][4];
    uint4  rb[2][2];

    // ldmatrix per-lane base byte offsets (within a stage)
    int r15 = lane & 15;
    uint32_t sAb = (uint32_t)__cvta_generic_to_shared(&sA[0][0]);
    uint32_t sBb = (uint32_t)__cvta_generic_to_shared(&sB[0][0]);
    uint32_t aoff = ((wm * 64 + r15) * STRIDE + ((lane >> 4) & 1) * 4) * 4;
    uint32_t boff = ((wn * 32 + (r15 & 7)) * STRIDE + ((r15 >> 3) & 1) * 4) * 4;

#define LOADG(IT, BK_)                                                         \
    {                                                                          \
        int k0 = (IT) * BK;                                                    \
        _Pragma("unroll")                                                      \
        for (int i = 0; i < 4; i++) {                                          \
            int f = tid + i * 256, m = f >> 3, q = f & 7;                      \
            ra[BK_][i] = *(const float4*)(inp + (size_t)(row0 + m) * LD_IN     \
                                          + A_OFF + k0 + q * 4);               \
        }                                                                      \
        _Pragma("unroll")                                                      \
        for (int i = 0; i < 2; i++) {                                          \
            int f = tid + i * 256, n = f >> 2, q = f & 3;                      \
            rb[BK_][i] = *(const uint4*)(g_SpT + (size_t)(col0 + n) * NSMP     \
                                         + k0 + q * 8);                        \
        }                                                                      \
        if (do_copy) {                                                         \
            _Pragma("unroll")                                                  \
            for (int i = 0; i < 4; i++) {                                      \
                int f = tid + i * 256, m = f >> 3, q = f & 7;                  \
                int gi = row0 + m, gj = k0 + q * 4;                            \
                float4 w = ra[BK_][i];                                         \
                int dlt = gi - gj;                                             \
                if (dlt >= 0 && dlt < 4) ((float*)&w)[dlt] += 1.0f;            \
                *(float4*)(out + (size_t)gi * LD_OUT + DOUT + gj) = w;         \
            }                                                                  \
        }                                                                      \
    }

#define STOS(S, BK_)                                                           \
    {                                                                          \
        _Pragma("unroll")                                                      \
        for (int i = 0; i < 4; i++) {                                          \
            int f = tid + i * 256, m = f >> 3, q = f & 7;                      \
            __nv_bfloat162 p0 = __floats2bfloat162_rn(ra[BK_][i].x, ra[BK_][i].y); \
            __nv_bfloat162 p1 = __floats2bfloat162_rn(ra[BK_][i].z, ra[BK_][i].w); \
            sA[S][m * STRIDE + q * 2]     = *(uint32_t*)&p0;                   \
            sA[S][m * STRIDE + q * 2 + 1] = *(uint32_t*)&p1;                   \
        }                                                                      \
        _Pragma("unroll")                                                      \
        for (int i = 0; i < 2; i++) {                                          \
            int f = tid + i * 256, n = f >> 2, q = f & 3;                      \
            sB[S][n * STRIDE + q * 4]     = rb[BK_][i].x;                      \
            sB[S][n * STRIDE + q * 4 + 1] = rb[BK_][i].y;                      \
            sB[S][n * STRIDE + q * 4 + 2] = rb[BK_][i].z;                      \
            sB[S][n * STRIDE + q * 4 + 3] = rb[BK_][i].w;                      \
        }                                                                      \
    }

#define COMPUTE(S)                                                             \
    {                                                                          \
        uint32_t aBase = sAb + (S) * ASZ + aoff;                               \
        uint32_t bBase = sBb + (S) * BSZ + boff;                               \
        _Pragma("unroll")                                                      \
        for (int ks = 0; ks < 2; ks++) {                                       \
            uint32_t af[4][4], bf[4][2];                                       \
            _Pragma("unroll")                                                  \
            for (int mt = 0; mt < 4; mt++)                                     \
                LDSM_X4(af[mt], aBase + mt * (16 * STRIDE * 4) + ks * 32);     \
            _Pragma("unroll")                                                  \
            for (int nt = 0; nt < 4; nt++)                                     \
                LDSM_X2(bf[nt], bBase + nt * (8 * STRIDE * 4) + ks * 32);      \
            _Pragma("unroll")                                                  \
            for (int mt = 0; mt < 4; mt++)                                     \
                _Pragma("unroll")                                              \
                for (int nt = 0; nt < 4; nt++)                                 \
                    mma16816(acc[mt][nt], af[mt], bf[nt]);                     \
        }                                                                      \
    }

    // prologue: depth-2 prefetch
    LOADG(0, 0);
    LOADG(1, 1);
    STOS(0, 0);
    __syncthreads();

#pragma unroll 1
    for (int it2 = 0; it2 < 128; ++it2) {
        int it = it2 * 2;
        // ---- even iteration: stage 0 ----
        COMPUTE(0);
        STOS(1, 1);
        if (it < 254) LOADG(it + 2, 0);
        __syncthreads();
        // ---- odd iteration: stage 1 ----
        COMPUTE(1);
        if (it + 1 < 255) STOS(0, 0);
        if (it + 1 < 254) LOADG(it + 3, 1);
        __syncthreads();
    }

    // ---- epilogue: out = dinv_i * (acc + S'_i) ----
#pragma unroll
    for (int mt = 0; mt < 4; mt++) {
        int r0 = row0 + wm * 64 + mt * 16 + g;
        int r1 = r0 + 8;
        float dv0 = g_dinv[r0], dv1 = g_dinv[r1];
#pragma unroll
        for (int nt = 0; nt < 4; nt++) {
            int c = col0 + wn * 32 + nt * 8 + tg * 2;
            const float* sp0 = g_Sp + (size_t)r0 * DOUT + c;
            const float* sp1 = g_Sp + (size_t)r1 * DOUT + c;
            float* o0 = out + (size_t)r0 * LD_OUT + c;
            float* o1 = out + (size_t)r1 * LD_OUT + c;
            o0[0] = dv0 * (acc[mt][nt][0] + sp0[0]);
            o0[1] = dv0 * (acc[mt][nt][1] + sp0[1]);
            o1[0] = dv1 * (acc[mt][nt][2] + sp1[0]);
            o1[1] = dv1 * (acc[mt][nt][3] + sp1[1]);
        }
    }
#undef LOADG
#undef STOS
#undef COMPUTE
}

// ---------------------------------------------------------------------------
extern "C" void kernel_launch(void* const* d_in, const int* in_sizes, int n_in,
                              void* d_out, int out_size) {
    const float* inp = (const float*)d_in[0];
    const float* W   = (const float*)d_in[1];
    float* out       = (float*)d_out;

    colsum_partial<<<dim3(NSMP / 256, 32), 256>>>(inp);
    colsum_finish<<<NSMP / 256, 256>>>();
    support_kernel<<<dim3(NSMP / 64, DOUT / 64), 256>>>(inp, W);
    main_gemm_mma<<<dim3(NSMP / BM, DOUT / BN), 256>>>(inp, out);
}